// round 1
// baseline (speedup 1.0000x reference)
#include <cuda_runtime.h>
#include <cuda_bf16.h>

// NonMaximaSuppression2d: x (8, 64, 256, 256) fp32.
// out = x * (x > max(0, 8-neighborhood max, replicate padding))
//
// B = N*C = 512 independent 256x256 images.
// Each thread handles 4 horizontally-adjacent outputs (float4 load/store).
// Per row (y-1, y, y+1): one aligned float4 + clamped left/right scalars.

#define H 256
#define W 256
#define WQ (W / 4)   // 64 float4 per row

__global__ __launch_bounds__(256, 8)
void nms2d_kernel(const float* __restrict__ x, float* __restrict__ out)
{
    const int q = threadIdx.x;                       // 0..63: float4 column index
    const int y = blockIdx.y * blockDim.y + threadIdx.y;
    const int b = blockIdx.z;                        // 0..511 (N*C)

    const size_t img = (size_t)b * (H * W);
    const float* __restrict__ base = x + img;

    const int ym = (y > 0)     ? y - 1 : 0;
    const int yp = (y < H - 1) ? y + 1 : H - 1;

    const int c0 = q * 4;
    const int cl = (c0 > 0) ? c0 - 1 : 0;            // clamped left column
    const int cr = (c0 + 4 < W) ? c0 + 4 : W - 1;    // clamped right column

    const float* rt = base + (size_t)ym * W;         // top row
    const float* rm = base + (size_t)y  * W;         // mid row
    const float* rb = base + (size_t)yp * W;         // bot row

    // Row loads: aligned float4 center + two scalar edges per row.
    const float4 tv = __ldg((const float4*)(rt) + q);
    const float  tl = __ldg(rt + cl);
    const float  tr = __ldg(rt + cr);

    const float4 mv = __ldg((const float4*)(rm) + q);
    const float  ml = __ldg(rm + cl);
    const float  mr = __ldg(rm + cr);

    const float4 bv = __ldg((const float4*)(rb) + q);
    const float  bl = __ldg(rb + cl);
    const float  br = __ldg(rb + cr);

    // 6-wide windows per row: [left, v.x, v.y, v.z, v.w, right]
    // Output j (j=0..3) neighborhood max:
    //   top[j], top[j+1], top[j+2], mid[j], mid[j+2], bot[j], bot[j+1], bot[j+2]
    // seeded with 0.0f (zeroed-center conv channel participates in the max).

    float t[6] = { tl, tv.x, tv.y, tv.z, tv.w, tr };
    float m[6] = { ml, mv.x, mv.y, mv.z, mv.w, mr };
    float g[6] = { bl, bv.x, bv.y, bv.z, bv.w, br };

    float4 o;
    {
        float mx = 0.0f;
        mx = fmaxf(mx, t[0]); mx = fmaxf(mx, t[1]); mx = fmaxf(mx, t[2]);
        mx = fmaxf(mx, m[0]);                        mx = fmaxf(mx, m[2]);
        mx = fmaxf(mx, g[0]); mx = fmaxf(mx, g[1]); mx = fmaxf(mx, g[2]);
        o.x = (mv.x > mx) ? mv.x : 0.0f;
    }
    {
        float mx = 0.0f;
        mx = fmaxf(mx, t[1]); mx = fmaxf(mx, t[2]); mx = fmaxf(mx, t[3]);
        mx = fmaxf(mx, m[1]);                        mx = fmaxf(mx, m[3]);
        mx = fmaxf(mx, g[1]); mx = fmaxf(mx, g[2]); mx = fmaxf(mx, g[3]);
        o.y = (mv.y > mx) ? mv.y : 0.0f;
    }
    {
        float mx = 0.0f;
        mx = fmaxf(mx, t[2]); mx = fmaxf(mx, t[3]); mx = fmaxf(mx, t[4]);
        mx = fmaxf(mx, m[2]);                        mx = fmaxf(mx, m[4]);
        mx = fmaxf(mx, g[2]); mx = fmaxf(mx, g[3]); mx = fmaxf(mx, g[4]);
        o.z = (mv.z > mx) ? mv.z : 0.0f;
    }
    {
        float mx = 0.0f;
        mx = fmaxf(mx, t[3]); mx = fmaxf(mx, t[4]); mx = fmaxf(mx, t[5]);
        mx = fmaxf(mx, m[3]);                        mx = fmaxf(mx, m[5]);
        mx = fmaxf(mx, g[3]); mx = fmaxf(mx, g[4]); mx = fmaxf(mx, g[5]);
        o.w = (mv.w > mx) ? mv.w : 0.0f;
    }

    ((float4*)(out + img + (size_t)y * W))[q] = o;
}

extern "C" void kernel_launch(void* const* d_in, const int* in_sizes, int n_in,
                              void* d_out, int out_size)
{
    const float* x = (const float*)d_in[0];
    float* out = (float*)d_out;

    // (8, 64, 256, 256) -> B = 512 images of 256x256
    dim3 block(WQ, 4, 1);          // 64 x 4 = 256 threads
    dim3 grid(1, H / 4, 8 * 64);   // (1, 64, 512)
    nms2d_kernel<<<grid, block>>>(x, out);
}